// round 12
// baseline (speedup 1.0000x reference)
#include <cuda_runtime.h>
#include <math_constants.h>

#define D_FEAT   128
#define K_NEIGH  32
#define WARPS_PER_CTA 4

// Map float -> uint preserving order (monotone), so integer max == float max.
__device__ __forceinline__ unsigned order_key(float f) {
    unsigned x = __float_as_uint(f);
    return (x & 0x80000000u) ? ~x : (x | 0x80000000u);
}

// One WARP per batch item, no shared memory (R9 structure, the proven best).
// The kernel runs at the practical LTS bandwidth cap; this version adds one
// more CTA/SM (launch_bounds occ=10 -> <=48 regs) by shrinking the winner-
// resolve batch from 10 to 2x5 (fewer live registers, MLP=5 per block on
// L1/L2-hot lines).
// Sim: 4 rows per pass, 8-lane groups with 128B-contiguous chunks; owner
// permutation lane 8g+p <- row 4p+g (no route shuffle; exact-sim ties only
// arise from duplicate neighbor indices whose rows are identical, so owner
// order is output-equivalent to jax.lax.top_k row-order tie-break).
// Key = dot * rsqrt(||n||^2) (center norm cancels for top-k).
// Selection: exact REDUX argmax rounds -> owner-lane bitmask; then blocked
// resolve+gather.
__global__ __launch_bounds__(WARPS_PER_CTA * 32, 10)
void intra_agg_kernel(const float*  __restrict__ feats,
                      const int*    __restrict__ nodes,
                      const int*    __restrict__ neighs,
                      const int*    __restrict__ nsamp_p,
                      float*        __restrict__ out)
{
    const int lane = threadIdx.x & 31;
    const int warp = threadIdx.x >> 5;
    const int b    = blockIdx.x * WARPS_PER_CTA + warp;
    const int g    = lane >> 3;        // group 0..3 (which row of the quad)
    const int t    = lane & 7;         // lane within group

    const float4* __restrict__ f4 = reinterpret_cast<const float4*>(feats);

    // ---- center row: this lane's 16-float column slice ----
    const int node = nodes[b];
    float4 c[4];
    #pragma unroll
    for (int j = 0; j < 4; j++)
        c[j] = f4[(size_t)node * (D_FEAT / 4) + t + 8 * j];

    // ---- my neighbor index (one coalesced 128B load) ----
    const int my_idx = neighs[b * K_NEIGH + lane];

    // ---- similarities: 8 passes x 4 rows; lane 8g+p keeps sim of row 4p+g ----
    float my_sim = 0.0f;
    #pragma unroll
    for (int p = 0; p < K_NEIGH / 4; p++) {
        const int nidx = __shfl_sync(0xffffffffu, my_idx, 4 * p + g);
        const float4* __restrict__ row = f4 + (size_t)nidx * (D_FEAT / 4);

        float dot = 0.0f, ss = 0.0f;
        #pragma unroll
        for (int j = 0; j < 4; j++) {
            const float4 v = row[t + 8 * j];
            dot = fmaf(v.x, c[j].x, fmaf(v.y, c[j].y,
                  fmaf(v.z, c[j].z, fmaf(v.w, c[j].w, dot))));
            ss  = fmaf(v.x, v.x, fmaf(v.y, v.y,
                  fmaf(v.z, v.z, fmaf(v.w, v.w, ss))));
        }
        // 3-stage butterfly within each 8-lane group (serves 4 rows at once)
        #pragma unroll
        for (int off = 1; off < 8; off <<= 1) {
            dot += __shfl_xor_sync(0xffffffffu, dot, off);
            ss  += __shfl_xor_sync(0xffffffffu, ss,  off);
        }
        if (t == p) my_sim = dot * rsqrtf(ss);   // owner lane 8g+p <- row 4p+g
    }

    const int ns = nsamp_p ? *nsamp_p : 10;

    // ---- top-ns selection: record winner OWNER lanes into a bitmask ----
    unsigned u = order_key(my_sim);
    unsigned wmask = 0u;
    for (int i = 0; i < ns; i++) {
        const unsigned m   = __reduce_max_sync(0xffffffffu, u);
        const unsigned msk = __ballot_sync(0xffffffffu, u == m);
        const int      w   = __ffs(msk) - 1;            // tie -> duplicate row
        if (lane == w) u = 0u;                          // below any real key
        wmask |= 1u << w;
    }

    // ---- blocked resolve + gather: 5 winners per block (low reg footprint,
    //      MLP=5 per block, loads mostly L1/L2-hot) ----
    float4 acc0 = make_float4(0.f, 0.f, 0.f, 0.f);
    float4 acc1 = make_float4(0.f, 0.f, 0.f, 0.f);
    while (wmask) {
        int nn[5];
        int cnt = 0;
        #pragma unroll
        for (int i = 0; i < 5; i++) {
            if (wmask) {
                const int w = __ffs(wmask) - 1;
                wmask &= wmask - 1;
                nn[i] = __shfl_sync(0xffffffffu, my_idx, 4 * (w & 7) + (w >> 3));
                cnt = i + 1;
            }
        }
        #pragma unroll
        for (int i = 0; i < 5; i++) {
            if (i < cnt) {
                const float4 v = f4[(size_t)nn[i] * (D_FEAT / 4) + lane];
                if (i & 1) { acc1.x += v.x; acc1.y += v.y; acc1.z += v.z; acc1.w += v.w; }
                else       { acc0.x += v.x; acc0.y += v.y; acc0.z += v.z; acc0.w += v.w; }
            }
        }
    }

    // ---- mean + relu, coalesced store ----
    const float inv = 1.0f / (float)ns;
    float4 r;
    r.x = fmaxf((acc0.x + acc1.x) * inv, 0.0f);
    r.y = fmaxf((acc0.y + acc1.y) * inv, 0.0f);
    r.z = fmaxf((acc0.z + acc1.z) * inv, 0.0f);
    r.w = fmaxf((acc0.w + acc1.w) * inv, 0.0f);
    reinterpret_cast<float4*>(out)[(size_t)b * (D_FEAT / 4) + lane] = r;
}

extern "C" void kernel_launch(void* const* d_in, const int* in_sizes, int n_in,
                              void* d_out, int out_size)
{
    const float* feats  = (const float*)d_in[0];   // [N_NODES, 128] f32
    const int*   nodes  = (const int*)d_in[1];     // [B] i32
    const int*   neighs = (const int*)d_in[2];     // [B, 32] i32
    const int*   nsamp  = (n_in > 3) ? (const int*)d_in[3] : nullptr;  // scalar (10)

    const int B = in_sizes[1];                     // 32768
    intra_agg_kernel<<<B / WARPS_PER_CTA, WARPS_PER_CTA * 32>>>(
        feats, nodes, neighs, nsamp, (float*)d_out);
}